// round 13
// baseline (speedup 1.0000x reference)
#include <cuda_runtime.h>
#include <cuda_bf16.h>
#include <mma.h>
#include <math_constants.h>
#include <cstdint>

using namespace nvcuda;

#define Nn 2
#define Ll 2048
#define Hh 8
#define Ee 64
#define Mm 2048
#define HEADS 16
#define NLH (HEADS*Ll)

#define NRM   0.3535533905932738f
#define HNRM2 0.0625f
#define RATIO 0.022097086912079608f
#define KEPS  1e-4f
#define EPSZ  1e-6f

// ---------------- scratch ----------------
__device__ float g_diag[2][NLH];
__device__ float g_pmax[(size_t)32*16*Ll];
__device__ float g_SUB[32*Ll];
__device__ __nv_bfloat16 g_Xhi[(size_t)2*HEADS*Ll*Ee];
__device__ __nv_bfloat16 g_Xlo[(size_t)2*HEADS*Ll*Ee];
__device__ __nv_bfloat16 g_Phi[(size_t)Mm*Ee];
__device__ __nv_bfloat16 g_Plo[(size_t)Mm*Ee];
__device__ __nv_bfloat16 g_VThi[(size_t)HEADS*Ee*Ll];
__device__ __nv_bfloat16 g_VTlo[(size_t)HEADS*Ee*Ll];
__device__ __nv_bfloat16 g_Bhi[(size_t)HEADS*80*Mm];   // rows 0-63 kv^T, row 64 ksum
__device__ __nv_bfloat16 g_Blo[(size_t)HEADS*80*Mm];

__device__ __forceinline__ void split1(float v, __nv_bfloat16& hi, __nv_bfloat16& lo) {
    hi = __float2bfloat16_rn(v);
    lo = __float2bfloat16_rn(v - __bfloat162float(hi));
}
__device__ __forceinline__ void split2pack(float a, float b, uint32_t& hi, uint32_t& lo) {
    __nv_bfloat16 ha, la, hb, lb;
    split1(a, ha, la); split1(b, hb, lb);
    __nv_bfloat162 H = __halves2bfloat162(ha, hb), L = __halves2bfloat162(la, lb);
    hi = *(uint32_t*)&H; lo = *(uint32_t*)&L;
}

__device__ __forceinline__ uint32_t smem_u32(const void* p) {
    uint32_t a;
    asm("{ .reg .u64 t; cvta.to.shared.u64 t, %1; cvt.u32.u64 %0, t; }" : "=r"(a) : "l"(p));
    return a;
}
__device__ __forceinline__ void cp16(uint32_t s, const void* g) {
    asm volatile("cp.async.cg.shared.global [%0], [%1], 16;" :: "r"(s), "l"(g));
}
#define CP_COMMIT() asm volatile("cp.async.commit_group;" ::: "memory")
#define CP_WAIT1()  asm volatile("cp.async.wait_group 1;" ::: "memory")
#define CP_WAIT0()  asm volatile("cp.async.wait_group 0;" ::: "memory")

typedef wmma::fragment<wmma::matrix_a, 16, 16, 16, __nv_bfloat16, wmma::row_major> FragA;
typedef wmma::fragment<wmma::matrix_b, 16, 16, 16, __nv_bfloat16, wmma::col_major> FragB;
typedef wmma::fragment<wmma::accumulator, 16, 16, 16, float> FragC;

// ================== K0: prep + vT split ==================
__global__ __launch_bounds__(256) void k_prepvt(const float* __restrict__ q,
                                                const float* __restrict__ kk,
                                                const float* __restrict__ P,
                                                const float* __restrict__ V)
{
    __shared__ __nv_bfloat16 sh[2][64][136];
    const int bx = blockIdx.x;
    const int tid = threadIdx.x;

    if (bx < 8448) {
        int g = bx * 256 + tid;
        int w = g >> 5, lane = g & 31;
        if (w < 2*NLH) {
            int which = (w >= NLH) ? 1 : 0;
            int r = which ? (w - NLH) : w;
            int head = r >> 11, l = r & (Ll - 1);
            int n = head >> 3, h = head & 7;
            const float* x = (which ? kk : q) + ((size_t)((n*Ll + l)*Hh + h))*Ee;
            float2 f = *(const float2*)(x + 2*lane);
            float s = f.x*f.x + f.y*f.y;
            #pragma unroll
            for (int o = 16; o; o >>= 1) s += __shfl_xor_sync(0xffffffffu, s, o);
            if (lane == 0) g_diag[which][r] = HNRM2 * s;
            uint32_t hi, lo; split2pack(f.x*NRM, f.y*NRM, hi, lo);
            size_t base = ((size_t)(which*HEADS + head)*Ll + l)*Ee;
            *(uint32_t*)(g_Xhi + base + 2*lane) = hi;
            *(uint32_t*)(g_Xlo + base + 2*lane) = lo;
        } else {
            int m = w - 2*NLH;
            const float* p = P + (size_t)m*Ee;
            float2 f = *(const float2*)(p + 2*lane);
            uint32_t hi, lo; split2pack(f.x, f.y, hi, lo);
            *(uint32_t*)(g_Phi + (size_t)m*Ee + 2*lane) = hi;
            *(uint32_t*)(g_Plo + (size_t)m*Ee + 2*lane) = lo;
        }
    } else {
        const int bvt = bx - 8448;
        const int head = bvt >> 4, n = head >> 3, h = head & 7;
        const int s0 = (bvt & 15) * 128;
        {
            int s = tid >> 1, eh = (tid & 1) * 32;
            const float* vp = V + ((size_t)((n*Ll + s0 + s)*Hh + h))*Ee + eh;
            #pragma unroll
            for (int j = 0; j < 8; j++) {
                float4 f = *(const float4*)(vp + j*4);
                float vv[4] = {f.x, f.y, f.z, f.w};
                #pragma unroll
                for (int i = 0; i < 4; i++) {
                    __nv_bfloat16 hb, lb; split1(vv[i], hb, lb);
                    int e = eh + j*4 + i;
                    sh[0][e][s] = hb;
                    sh[1][e][s] = lb;
                }
            }
        }
        __syncthreads();
        {
            int e = tid >> 2, sc = (tid & 3) * 32;
            #pragma unroll
            for (int p = 0; p < 2; p++) {
                __nv_bfloat16* dst = (p ? g_VTlo : g_VThi) + ((size_t)(head*Ee + e))*Ll + s0 + sc;
                const uint32_t* src = (const uint32_t*)&sh[p][e][sc];
                #pragma unroll
                for (int i = 0; i < 16; i++) ((uint32_t*)dst)[i] = src[i];
            }
        }
    }
}

// ================== K1: rowmax pass (k_feat minus global store) ==========
#define FT_A     36864
#define FT_STG   110592
#define FT_SMEM  178176
__global__ __launch_bounds__(512, 1) void k_max()
{
    extern __shared__ char smem[];
    const uint32_t sb = smem_u32(smem);
    const int wh = blockIdx.z;
    const int m0 = blockIdx.x * 128;
    const int lbase = blockIdx.y * 1024;
    const int tid = threadIdx.x, wid = tid >> 5;

    const __nv_bfloat16* Xhi = g_Xhi + (size_t)wh*Ll*Ee;
    const __nv_bfloat16* Xlo = g_Xlo + (size_t)wh*Ll*Ee;

    #pragma unroll
    for (int j = 0; j < 4; j++) {
        int g = tid + j*512;
        int plane = g >> 10, r = (g >> 3) & 127, c = g & 7;
        const __nv_bfloat16* src = (plane ? g_Plo : g_Phi) + (size_t)(m0 + r)*Ee + c*8;
        cp16(sb + plane*18432 + (r*72 + c*8)*2, src);
    }
    #pragma unroll
    for (int j = 0; j < 4; j++) {
        int g = tid + j*512;
        int plane = g >> 10, r = (g >> 3) & 127, c = g & 7;
        const __nv_bfloat16* src = (plane ? Xlo : Xhi) + (size_t)(lbase + r)*Ee + c*8;
        cp16(sb + FT_A + plane*18432 + (r*72 + c*8)*2, src);
    }
    CP_COMMIT();
    #pragma unroll
    for (int j = 0; j < 4; j++) {
        int g = tid + j*512;
        int plane = g >> 10, r = (g >> 3) & 127, c = g & 7;
        const __nv_bfloat16* src = (plane ? Xlo : Xhi) + (size_t)(lbase + 128 + r)*Ee + c*8;
        cp16(sb + FT_A + 36864 + plane*18432 + (r*72 + c*8)*2, src);
    }
    CP_COMMIT();

    const int warp_l = (wid & 3) * 32, warp_m = (wid >> 2) * 32;
    float* stage = (float*)(smem + FT_STG);
    const __nv_bfloat16* Bhi = (const __nv_bfloat16*)smem;
    const __nv_bfloat16* Blo = Bhi + 9216;

    for (int t = 0; t < 8; t++) {
        if (t < 7) { CP_WAIT1(); } else { CP_WAIT0(); }
        __syncthreads();

        const __nv_bfloat16* Ahi = (const __nv_bfloat16*)(smem + FT_A + (t & 1)*36864);
        const __nv_bfloat16* Alo = Ahi + 9216;

        FragC c[2][2];
        #pragma unroll
        for (int i = 0; i < 2; i++)
            #pragma unroll
            for (int j = 0; j < 2; j++) wmma::fill_fragment(c[i][j], 0.0f);

        #pragma unroll
        for (int k = 0; k < 4; k++) {
            FragA ahi[2], alo[2];
            #pragma unroll
            for (int i = 0; i < 2; i++) {
                wmma::load_matrix_sync(ahi[i], Ahi + (warp_l + i*16)*72 + k*16, 72);
                wmma::load_matrix_sync(alo[i], Alo + (warp_l + i*16)*72 + k*16, 72);
            }
            #pragma unroll
            for (int j = 0; j < 2; j++) {
                FragB bhi, blo;
                wmma::load_matrix_sync(bhi, Bhi + (warp_m + j*16)*72 + k*16, 72);
                wmma::load_matrix_sync(blo, Blo + (warp_m + j*16)*72 + k*16, 72);
                #pragma unroll
                for (int i = 0; i < 2; i++) {
                    wmma::mma_sync(c[i][j], ahi[i], bhi, c[i][j]);
                    wmma::mma_sync(c[i][j], ahi[i], blo, c[i][j]);
                    wmma::mma_sync(c[i][j], alo[i], bhi, c[i][j]);
                }
            }
        }

        #pragma unroll
        for (int i = 0; i < 2; i++)
            #pragma unroll
            for (int j = 0; j < 2; j++)
                wmma::store_matrix_sync(stage + (warp_l + i*16)*132 + warp_m + j*16,
                                        c[i][j], 132, wmma::mem_row_major);
        __syncthreads();

        if (t + 2 < 8) {
            #pragma unroll
            for (int j = 0; j < 4; j++) {
                int g = tid + j*512;
                int plane = g >> 10, r = (g >> 3) & 127, cc = g & 7;
                const __nv_bfloat16* src = (plane ? Xlo : Xhi)
                    + (size_t)(lbase + (t + 2)*128 + r)*Ee + cc*8;
                cp16(sb + FT_A + (t & 1)*36864 + plane*18432 + (r*72 + cc*8)*2, src);
            }
            CP_COMMIT();
        }

        {
            int row = tid >> 2;
            int l = lbase + t*128 + row;
            float rm = -CUDART_INF_F;
            const float* srcr = stage + row*132;
            #pragma unroll
            for (int j = 0; j < 8; j++) {
                int col = (tid & 3)*4 + j*16;
                float4 v = *(const float4*)(srcr + col);
                rm = fmaxf(rm, fmaxf(fmaxf(v.x, v.y), fmaxf(v.z, v.w)));
            }
            rm = fmaxf(rm, __shfl_xor_sync(0xffffffffu, rm, 1));
            rm = fmaxf(rm, __shfl_xor_sync(0xffffffffu, rm, 2));
            if ((tid & 3) == 0)
                g_pmax[((size_t)wh*16 + blockIdx.x)*Ll + l] = rm;
        }
    }
}

// ================== K1b: rowmax reduce + diag fold ==================
__global__ __launch_bounds__(256) void k_rmax()
{
    int gw = (blockIdx.x * 256 + threadIdx.x) >> 5;
    int lane = threadIdx.x & 31;
    int wh = gw >> 6;
    int l = (gw & 63) * 32 + lane;
    float m = -CUDART_INF_F;
    #pragma unroll
    for (int mt = 0; mt < 16; mt++)
        m = fmaxf(m, g_pmax[((size_t)wh*16 + mt)*Ll + l]);
    g_SUB[wh*Ll + l] = g_diag[wh >> 4][(wh & 15)*Ll + l] + m;
}

// ================== K2: fused kv — recompute dash_k, exp, kv MMA ==========
// CTA = (m-tile 128, head). 32 halves of 64 s.
// smem: P 36864 @0 | X 2x18432 @36864 | B(VT) 3x18432 @73728 | Ah/Al @129024
//       stage 64x132f @163840 | SUB 8192 @197632 | KS 512 @205824
#define KVF_X     36864
#define KVF_B     73728
#define KVF_A     129024
#define KVF_STG   163840
#define KVF_SUB   197632
#define KVF_KS    205824
#define KVF_SMEM  206336
__global__ __launch_bounds__(512, 1) void k_kvf()
{
    extern __shared__ char smem[];
    const uint32_t sb = smem_u32(smem);
    float* SUB = (float*)(smem + KVF_SUB);
    float* KS  = (float*)(smem + KVF_KS);

    const int head = blockIdx.y;
    const int m0 = blockIdx.x * 128;
    const int tid = threadIdx.x, wid = tid >> 5;
    const int whk = 16 + head;

    // P resident (goes into group 0)
    #pragma unroll
    for (int j = 0; j < 4; j++) {
        int g = tid + j*512;
        int plane = g >> 10, r = (g >> 3) & 127, c = g & 7;
        const __nv_bfloat16* src = (plane ? g_Plo : g_Phi) + (size_t)(m0 + r)*Ee + c*8;
        cp16(sb + plane*18432 + (r*72 + c*8)*2, src);
    }
    // X(0),B(0) -> group0 ; X(1),B(1) -> group1
    #pragma unroll
    for (int tt = 0; tt < 2; tt++) {
        #pragma unroll
        for (int j = 0; j < 2; j++) {
            int g = tid + j*512;
            int plane = g >> 9, rem = g & 511, row = rem >> 3, c = rem & 7;
            const __nv_bfloat16* src = (plane ? g_Xlo : g_Xhi)
                + ((size_t)(whk*Ll) + tt*64 + row)*Ee + c*8;
            cp16(sb + KVF_X + tt*18432 + plane*9216 + (row*72 + c*8)*2, src);
        }
        #pragma unroll
        for (int j = 0; j < 2; j++) {
            int g = tid + j*512;
            int plane = g >> 9, rem = g & 511, row = rem >> 3, c = rem & 7;
            const __nv_bfloat16* src = (plane ? g_VTlo : g_VThi)
                + (size_t)(head*Ee + row)*Ll + tt*64 + c*8;
            cp16(sb + KVF_B + tt*18432 + plane*9216 + (row*72 + c*8)*2, src);
        }
        CP_COMMIT();
    }

    for (int i = tid; i < 2048; i += 512)
        SUB[i] = g_SUB[whk*Ll + i];
    if (tid < 128) KS[tid] = 0.0f;

    const int warp_s  = (wid & 3) * 16, warp_m1 = (wid >> 2) * 32;   // MMA1 4x4
    const int warp_m2 = (wid & 7) * 16, warp_e  = (wid >> 3) * 32;   // MMA2 8x2
    const int mT = tid & 127, sg = (tid >> 7) * 16;                  // transform

    float* stage = (float*)(smem + KVF_STG);
    const __nv_bfloat16* PH = (const __nv_bfloat16*)smem;
    const __nv_bfloat16* PL = PH + 9216;
    __nv_bfloat16* Ah = (__nv_bfloat16*)(smem + KVF_A);
    __nv_bfloat16* Al = Ah + 8704;    // 17408 bytes per plane

    FragC c2[2];
    wmma::fill_fragment(c2[0], 0.0f);
    wmma::fill_fragment(c2[1], 0.0f);
    float ksp = 0.0f;

    for (int t = 0; t < 32; t++) {
        if (t < 31) { CP_WAIT1(); } else { CP_WAIT0(); }
        __syncthreads();                                   // X(t),B(t) visible

        // MMA1: dash[64s x 128m] = Xk(t) @ P^T
        {
            const __nv_bfloat16* Xh = (const __nv_bfloat16*)(smem + KVF_X + (t & 1)*18432);
            const __nv_bfloat16* Xl = Xh + 4608;           // 9216 bytes
            FragC c1[2];
            wmma::fill_fragment(c1[0], 0.0f);
            wmma::fill_fragment(c1[1], 0.0f);
            #pragma unroll
            for (int k = 0; k < 4; k++) {
                FragA axh, axl;
                wmma::load_matrix_sync(axh, Xh + warp_s*72 + k*16, 72);
                wmma::load_matrix_sync(axl, Xl + warp_s*72 + k*16, 72);
                #pragma unroll
                for (int j = 0; j < 2; j++) {
                    FragB bph, bpl;
                    wmma::load_matrix_sync(bph, PH + (warp_m1 + j*16)*72 + k*16, 72);
                    wmma::load_matrix_sync(bpl, PL + (warp_m1 + j*16)*72 + k*16, 72);
                    wmma::mma_sync(c1[j], axh, bph, c1[j]);
                    wmma::mma_sync(c1[j], axh, bpl, c1[j]);
                    wmma::mma_sync(c1[j], axl, bph, c1[j]);
                }
            }
            #pragma unroll
            for (int j = 0; j < 2; j++)
                wmma::store_matrix_sync(stage + warp_s*132 + warp_m1 + j*16,
                                        c1[j], 132, wmma::mem_row_major);
        }
        __syncthreads();                                   // stage ready; X(t) consumed

        // transform: k' = RATIO*(exp(dash - SUB) + KEPS), split into A [m][s] ld 68
        {
            const float* subp = SUB + t*64 + sg;
            #pragma unroll
            for (int i = 0; i < 16; i += 2) {
                float f0 = stage[(sg + i)*132 + mT];
                float f1 = stage[(sg + i + 1)*132 + mT];
                float k0 = RATIO * (__expf(f0 - subp[i])   + KEPS);
                float k1 = RATIO * (__expf(f1 - subp[i+1]) + KEPS);
                ksp += k0 + k1;
                uint32_t hi, lo; split2pack(k0, k1, hi, lo);
                *(uint32_t*)&Ah[mT*68 + sg + i] = hi;
                *(uint32_t*)&Al[mT*68 + sg + i] = lo;
            }
        }
        __syncthreads();                                   // A ready

        if (t + 2 < 32) {                                  // refill X (t&1), B ((t+2)%3)
            const int s1 = (t + 2) * 64;
            #pragma unroll
            for (int j = 0; j < 2; j++) {
                int g = tid + j*512;
                int plane = g >> 9, rem = g & 511, row = rem >> 3, c = rem & 7;
                const __nv_bfloat16* src = (plane ? g_Xlo : g_Xhi)
                    + ((size_t)(whk*Ll) + s1 + row)*Ee + c*8;
                cp16(sb + KVF_X + (t & 1)*18432 + plane*9216 + (row*72 + c*8)*2, src);
            }
            #pragma unroll
            for (int j = 0; j < 2; j++) {
                int g = tid + j*512;
                int plane = g >> 9, rem = g & 511, row = rem >> 3, c = rem & 7;
                const __nv_bfloat16* src = (plane ? g_VTlo : g_VThi)
                    + (size_t)(head*Ee + row)*Ll + s1 + c*8;
                cp16(sb + KVF_B + ((t + 2) % 3)*18432 + plane*9216 + (row*72 + c*8)*2, src);
            }
            CP_COMMIT();
        }

        // MMA2: kv[128m x 64e] += k'(A) @ VT(B)
        {
            const __nv_bfloat16* Bh = (const __nv_bfloat16*)(smem + KVF_B + (t % 3)*18432);
            const __nv_bfloat16* Bl = Bh + 4608;
            #pragma unroll
            for (int k = 0; k < 4; k++) {
                FragA aah, aal;
                wmma::load_matrix_sync(aah, Ah + warp_m2*68 + k*16, 68);
                wmma::load_matrix_sync(aal, Al + warp_m2*68 + k*16, 68);
                #pragma unroll
                for (int j = 0; j < 2; j++) {
                    FragB bvh, bvl;
                    wmma::load_matrix_sync(bvh, Bh + (warp_e + j*16)*72 + k*16, 72);
                    wmma::load_matrix_sync(bvl, Bl + (warp_e + j*16)*72 + k*16, 72);
                    wmma::mma_sync(c2[j], aah, bvh, c2[j]);
                    wmma::mma_sync(c2[j], aah, bvl, c2[j]);
                    wmma::mma_sync(c2[j], aal, bvh, c2[j]);
                }
            }
        }
    }

    atomicAdd(&KS[mT], ksp);
    __syncthreads();
    // stage kv as [e][m] (col-major store)
    #pragma unroll
    for (int j = 0; j < 2; j++)
        wmma::store_matrix_sync(stage + warp_m2 + (warp_e + j*16)*132,
                                c2[j], 132, wmma::mem_col_major);
    __syncthreads();
    {
        int e = tid >> 3, mo = (tid & 7) * 16;
        const float* src = stage + e*132 + mo;
        __nv_bfloat16* dhi = g_Bhi + (size_t)(head*80 + e)*Mm + m0 + mo;
        __nv_bfloat16* dlo = g_Blo + (size_t)(head*80 + e)*Mm + m0 + mo;
        #pragma unroll
        for (int j = 0; j < 16; j += 2) {
            uint32_t hi, lo; split2pack(src[j], src[j+1], hi, lo);
            *(uint32_t*)(dhi + j) = hi;
            *(uint32_t*)(dlo + j) = lo;
        }
    }
    if (tid < 128) {
        __nv_bfloat16 hb, lb; split1(KS[tid], hb, lb);
        g_Bhi[(size_t)(head*80 + 64)*Mm + m0 + tid] = hb;
        g_Blo[(size_t)(head*80 + 64)*Mm + m0 + tid] = lb;
    }
}

// ================== K3: fused out — recompute dash_q, exp, out MMA ========
// CTA = (l-tile 128, head). 32 halves of 64 m.
// smem: Xq 36864 @0 | P 2x18432 @36864 | B 3x23040 @73728 | Ah/Al @142848
//       stage 128x68f @177664 | SUBL 512 @212480
#define OF_P     36864
#define OF_B     73728
#define OF_A     142848
#define OF_STG   177664
#define OF_SUBL  212480
#define OF_SMEM  212992
__global__ __launch_bounds__(512, 1) void k_outf(float* __restrict__ out)
{
    extern __shared__ char smem[];
    const uint32_t sb = smem_u32(smem);
    float* SUBL = (float*)(smem + OF_SUBL);

    const int head = blockIdx.y, n = head >> 3, h = head & 7;
    const int l0 = blockIdx.x * 128;
    const int tid = threadIdx.x, wid = tid >> 5;

    // Xq resident (group 0)
    #pragma unroll
    for (int j = 0; j < 4; j++) {
        int g = tid + j*512;
        int plane = g >> 10, r = (g >> 3) & 127, c = g & 7;
        const __nv_bfloat16* src = (plane ? g_Xlo : g_Xhi)
            + ((size_t)(head*Ll) + l0 + r)*Ee + c*8;
        cp16(sb + plane*18432 + (r*72 + c*8)*2, src);
    }
    // P(0),B(0) -> group0 ; P(1),B(1) -> group1
    #pragma unroll
    for (int tt = 0; tt < 2; tt++) {
        #pragma unroll
        for (int j = 0; j < 2; j++) {
            int g = tid + j*512;
            int plane = g >> 9, rem = g & 511, row = rem >> 3, c = rem & 7;
            const __nv_bfloat16* src = (plane ? g_Plo : g_Phi)
                + (size_t)(tt*64 + row)*Ee + c*8;
            cp16(sb + OF_P + tt*18432 + plane*9216 + (row*72 + c*8)*2, src);
        }
        #pragma unroll
        for (int j = 0; j < 3; j++) {
            int g = tid + j*512;
            if (g < 1280) {
                int plane = g / 640, rem = g % 640, row = rem >> 3, c = rem & 7;
                const __nv_bfloat16* src = (plane ? g_Blo : g_Bhi)
                    + (size_t)(head*80 + row)*Mm + tt*64 + c*8;
                cp16(sb + OF_B + tt*23040 + plane*11520 + (row*72 + c*8)*2, src);
            }
        }
        CP_COMMIT();
    }

    if (tid < 128)
        SUBL[tid] = g_SUB[head*Ll + l0 + tid];

    const int warp_l1 = (wid & 3) * 32, warp_m1 = (wid >> 2) * 16;   // MMA1 4x4
    const int warp_l2 = (wid & 7) * 16, grp = wid >> 3;              // MMA2 8x2
    const int jb  = grp ? 3 : 0;
    const int nfr = grp ? 2 : 3;
    const int lT = tid >> 2, mg = (tid & 3) * 16;                    // transform

    float* stage = (float*)(smem + OF_STG);
    const __nv_bfloat16* XH = (const __nv_bfloat16*)smem;
    const __nv_bfloat16* XL = XH + 9216;
    __nv_bfloat16* Ah = (__nv_bfloat16*)(smem + OF_A);
    __nv_bfloat16* Al = Ah + 8704;

    FragC c2[3];
    #pragma unroll
    for (int j = 0; j < 3; j++) wmma::fill_fragment(c2[j], 0.0f);

    for (int t = 0; t < 32; t++) {
        if (t < 31) { CP_WAIT1(); } else { CP_WAIT0(); }
        __syncthreads();                                   // P(t),B(t) visible

        // MMA1: dash[128l x 64m] = Xq @ P(t)^T
        {
            const __nv_bfloat16* Ph = (const __nv_bfloat16*)(smem + OF_P + (t & 1)*18432);
            const __nv_bfloat16* Pl = Ph + 4608;
            FragC c1[2];
            wmma::fill_fragment(c1[0], 0.0f);
            wmma::fill_fragment(c1[1], 0.0f);
            #pragma unroll
            for (int k = 0; k < 4; k++) {
                FragB bph, bpl;
                wmma::load_matrix_sync(bph, Ph + warp_m1*72 + k*16, 72);
                wmma::load_matrix_sync(bpl, Pl + warp_m1*72 + k*16, 72);
                #pragma unroll
                for (int i = 0; i < 2; i++) {
                    FragA axh, axl;
                    wmma::load_matrix_sync(axh, XH + (warp_l1 + i*16)*72 + k*16, 72);
                    wmma::load_matrix_sync(axl, XL + (warp_l1 + i*16)*72 + k*16, 72);
                    wmma::mma_sync(c1[i], axh, bph, c1[i]);
                    wmma::mma_sync(c1[i], axh, bpl, c1[i]);
                    wmma::mma_sync(c1[i], axl, bph, c1[i]);
                }
            }
            #pragma unroll
            for (int i = 0; i < 2; i++)
                wmma::store_matrix_sync(stage + (warp_l1 + i*16)*68 + warp_m1,
                                        c1[i], 68, wmma::mem_row_major);
        }
        __syncthreads();                                   // stage ready

        // transform: q' split into A [l][m] ld 68
        {
            const float sub = SUBL[lT];
            #pragma unroll
            for (int i = 0; i < 16; i += 2) {
                float f0 = stage[lT*68 + mg + i];
                float f1 = stage[lT*68 + mg + i + 1];
                float q0 = RATIO * (__expf(f0 - sub) + KEPS);
                float q1 = RATIO * (__expf(f1 - sub) + KEPS);
                uint32_t hi, lo; split2pack(q0, q1, hi, lo);
                *(uint32_t*)&Ah[lT*68 + mg + i] = hi;
                *(uint32_t*)&Al[lT*68 + mg + i] = lo;
            }
        }
        __syncthreads();                                   // A ready

        if (t + 2 < 32) {
            const int m1 = (t + 2) * 64;
            #pragma unroll
            for (int j = 0; j < 2; j++) {
                int g = tid + j*512;
                int plane = g >> 9, rem = g & 511, row = rem >> 3, c = rem & 7;
                const __nv_bfloat16* src = (plane ? g_Plo : g_Phi)
                    + (size_t)(m1 + row)*Ee + c*8;
                cp16(sb + OF_P + (t & 1)*18432 + plane*9216 + (row*72 + c*8)*2, src);
            }
            #pragma unroll
            for (int j = 0; j < 3; j++) {
                int g = tid + j*512;
                if (g < 1280) {
                    int plane = g / 640, rem = g % 640, row = rem >> 3, c = rem & 7;
                    const __nv_bfloat16* src = (plane ? g_Blo : g_Bhi)
                        + (size_t)(head*80 + row)*Mm + m1 + c*8;
                    cp16(sb + OF_B + ((t + 2) % 3)*23040 + plane*11520 + (row*72 + c*8)*2, src);
                }
            }
            CP_COMMIT();
        }

        // MMA2: C[128l x 80] += q'(A) @ B(t)
        {
            const __nv_bfloat16* Bh = (const __nv_bfloat16*)(smem + OF_B + (t % 3)*23040);
            const __nv_bfloat16* Bl = Bh + 5760;           // 11520 bytes
            #pragma unroll
            for (int k = 0; k < 4; k++) {
                FragA aah, aal;
                wmma::load_matrix_sync(aah, Ah + warp_l2*68 + k*16, 68);
                wmma::load_matrix_sync(aal, Al + warp_l2*68 + k*16, 68);
                for (int j = 0; j < nfr; j++) {
                    FragB bh, bl;
                    wmma::load_matrix_sync(bh, Bh + ((jb + j)*16)*72 + k*16, 72);
                    wmma::load_matrix_sync(bl, Bl + ((jb + j)*16)*72 + k*16, 72);
                    wmma::mma_sync(c2[j], aah, bh, c2[j]);
                    wmma::mma_sync(c2[j], aah, bl, c2[j]);
                    wmma::mma_sync(c2[j], aal, bh, c2[j]);
                }
            }
        }
    }

    __syncthreads();
    float* stage84 = (float*)smem;    // [128 l][84] over dead Xq/P regions
    for (int j = 0; j < nfr; j++)
        wmma::store_matrix_sync(stage84 + warp_l2*84 + (jb + j)*16, c2[j], 84,
                                wmma::mem_row_major);
    __syncthreads();
    {
        int l = tid >> 2, ec = (tid & 3) * 16;
        float z = 1.0f / (stage84[l*84 + 64] + EPSZ);
        float* dst = out + ((size_t)((n*Ll + l0 + l)*Hh + h))*Ee + ec;
        const float* src = stage84 + l*84 + ec;
        #pragma unroll
        for (int j = 0; j < 4; j++) {
            float4 v = *(const float4*)(src + j*4);
            *(float4*)(dst + j*4) = make_float4(v.x*z, v.y*z, v.z*z, v.w*z);
        }
    }
}

// ================== launch ==================
extern "C" void kernel_launch(void* const* d_in, const int* in_sizes, int n_in,
                              void* d_out, int out_size)
{
    const float* q = (const float*)d_in[0];
    const float* k = (const float*)d_in[1];
    const float* v = (const float*)d_in[2];
    const float* p = (const float*)d_in[3];
    float* out = (float*)d_out;

    cudaFuncSetAttribute(k_max,  cudaFuncAttributeMaxDynamicSharedMemorySize, FT_SMEM);
    cudaFuncSetAttribute(k_kvf,  cudaFuncAttributeMaxDynamicSharedMemorySize, KVF_SMEM);
    cudaFuncSetAttribute(k_outf, cudaFuncAttributeMaxDynamicSharedMemorySize, OF_SMEM);

    k_prepvt<<<8704, 256>>>(q, k, p, v);
    k_max<<<dim3(16, 2, 32), 512, FT_SMEM>>>();
    k_rmax<<<256, 256>>>();
    k_kvf<<<dim3(16, HEADS), 512, KVF_SMEM>>>();
    k_outf<<<dim3(16, HEADS), 512, OF_SMEM>>>(out);
}

// round 14
// speedup vs baseline: 1.3314x; 1.3314x over previous
#include <cuda_runtime.h>
#include <cuda_bf16.h>
#include <mma.h>
#include <math_constants.h>
#include <cstdint>

using namespace nvcuda;

#define Nn 2
#define Ll 2048
#define Hh 8
#define Ee 64
#define Mm 2048
#define HEADS 16
#define NLH (HEADS*Ll)

#define NRM   0.3535533905932738f
#define HNRM2 0.0625f
#define RATIO 0.022097086912079608f
#define KEPS  1e-4f
#define EPSZ  1e-6f

// ---------------- scratch ----------------
__device__ float g_Dq[(size_t)HEADS*Ll*Mm];
__device__ float g_Dk[(size_t)HEADS*Ll*Mm];
__device__ float g_diag[2][NLH];
__device__ float g_pmax[(size_t)32*16*Ll];
__device__ float g_SUB[32*Ll];
__device__ __nv_bfloat16 g_Xhi[(size_t)2*HEADS*Ll*Ee];
__device__ __nv_bfloat16 g_Xlo[(size_t)2*HEADS*Ll*Ee];
__device__ __nv_bfloat16 g_Phi[(size_t)Mm*Ee];
__device__ __nv_bfloat16 g_Plo[(size_t)Mm*Ee];
__device__ __nv_bfloat16 g_VThi[(size_t)HEADS*Ee*Ll];
__device__ __nv_bfloat16 g_VTlo[(size_t)HEADS*Ee*Ll];
__device__ __nv_bfloat16 g_Bhi[(size_t)HEADS*80*Mm];   // rows 0-63 kv^T, row 64 ksum
__device__ __nv_bfloat16 g_Blo[(size_t)HEADS*80*Mm];

__device__ __forceinline__ void split1(float v, __nv_bfloat16& hi, __nv_bfloat16& lo) {
    hi = __float2bfloat16_rn(v);
    lo = __float2bfloat16_rn(v - __bfloat162float(hi));
}
__device__ __forceinline__ void split2pack(float a, float b, uint32_t& hi, uint32_t& lo) {
    __nv_bfloat16 ha, la, hb, lb;
    split1(a, ha, la); split1(b, hb, lb);
    __nv_bfloat162 H = __halves2bfloat162(ha, hb), L = __halves2bfloat162(la, lb);
    hi = *(uint32_t*)&H; lo = *(uint32_t*)&L;
}

__device__ __forceinline__ uint32_t smem_u32(const void* p) {
    uint32_t a;
    asm("{ .reg .u64 t; cvta.to.shared.u64 t, %1; cvt.u32.u64 %0, t; }" : "=r"(a) : "l"(p));
    return a;
}
__device__ __forceinline__ void cp16(uint32_t s, const void* g) {
    asm volatile("cp.async.cg.shared.global [%0], [%1], 16;" :: "r"(s), "l"(g));
}
#define CP_COMMIT() asm volatile("cp.async.commit_group;" ::: "memory")
#define CP_WAIT1()  asm volatile("cp.async.wait_group 1;" ::: "memory")
#define CP_WAIT0()  asm volatile("cp.async.wait_group 0;" ::: "memory")

typedef wmma::fragment<wmma::matrix_a, 16, 16, 16, __nv_bfloat16, wmma::row_major> FragA;
typedef wmma::fragment<wmma::matrix_b, 16, 16, 16, __nv_bfloat16, wmma::col_major> FragB;
typedef wmma::fragment<wmma::accumulator, 16, 16, 16, float> FragC;

// ================== K0: prep ==================
__global__ __launch_bounds__(256) void k_prep(const float* __restrict__ q,
                                              const float* __restrict__ kk,
                                              const float* __restrict__ P)
{
    int g = blockIdx.x * 256 + threadIdx.x;
    int w = g >> 5, lane = g & 31;
    if (w < 2*NLH) {
        int which = (w >= NLH) ? 1 : 0;
        int r = which ? (w - NLH) : w;
        int head = r >> 11, l = r & (Ll - 1);
        int n = head >> 3, h = head & 7;
        const float* x = (which ? kk : q) + ((size_t)((n*Ll + l)*Hh + h))*Ee;
        float2 f = *(const float2*)(x + 2*lane);
        float s = f.x*f.x + f.y*f.y;
        #pragma unroll
        for (int o = 16; o; o >>= 1) s += __shfl_xor_sync(0xffffffffu, s, o);
        if (lane == 0) g_diag[which][r] = HNRM2 * s;
        uint32_t hi, lo; split2pack(f.x*NRM, f.y*NRM, hi, lo);
        size_t base = ((size_t)(which*HEADS + head)*Ll + l)*Ee;
        *(uint32_t*)(g_Xhi + base + 2*lane) = hi;
        *(uint32_t*)(g_Xlo + base + 2*lane) = lo;
    } else {
        int m = w - 2*NLH;
        const float* p = P + (size_t)m*Ee;
        float2 f = *(const float2*)(p + 2*lane);
        uint32_t hi, lo; split2pack(f.x, f.y, hi, lo);
        *(uint32_t*)(g_Phi + (size_t)m*Ee + 2*lane) = hi;
        *(uint32_t*)(g_Plo + (size_t)m*Ee + 2*lane) = lo;
    }
}

// ================== K0b: v -> vT split ==================
__global__ __launch_bounds__(256) void k_vt(const float* __restrict__ V)
{
    __shared__ __nv_bfloat16 sh[2][64][136];
    const int head = blockIdx.y, n = head >> 3, h = head & 7;
    const int s0 = blockIdx.x * 128;
    const int tid = threadIdx.x;

    {
        int s = tid >> 1, eh = (tid & 1) * 32;
        const float* vp = V + ((size_t)((n*Ll + s0 + s)*Hh + h))*Ee + eh;
        #pragma unroll
        for (int j = 0; j < 8; j++) {
            float4 f = *(const float4*)(vp + j*4);
            float vv[4] = {f.x, f.y, f.z, f.w};
            #pragma unroll
            for (int i = 0; i < 4; i++) {
                __nv_bfloat16 hb, lb; split1(vv[i], hb, lb);
                int e = eh + j*4 + i;
                sh[0][e][s] = hb;
                sh[1][e][s] = lb;
            }
        }
    }
    __syncthreads();
    {
        int e = tid >> 2, sc = (tid & 3) * 32;
        #pragma unroll
        for (int p = 0; p < 2; p++) {
            __nv_bfloat16* dst = (p ? g_VTlo : g_VThi) + ((size_t)(head*Ee + e))*Ll + s0 + sc;
            const uint32_t* src = (const uint32_t*)&sh[p][e][sc];
            #pragma unroll
            for (int i = 0; i < 16; i++) ((uint32_t*)dst)[i] = src[i];
        }
    }
}

// ================== K1: featurize — persistent stripe (8 tiles) ==========
#define FT_A     36864
#define FT_STG   110592
#define FT_SMEM  178176
__global__ __launch_bounds__(512, 1) void k_feat()
{
    extern __shared__ char smem[];
    const uint32_t sb = smem_u32(smem);
    const int wh = blockIdx.z;
    const int which = wh >> 4, head = wh & 15;
    const int m0 = blockIdx.x * 128;
    const int lbase = blockIdx.y * 1024;
    const int tid = threadIdx.x, wid = tid >> 5;
    float* __restrict__ Dash = which ? g_Dk : g_Dq;

    const __nv_bfloat16* Xhi = g_Xhi + (size_t)wh*Ll*Ee;
    const __nv_bfloat16* Xlo = g_Xlo + (size_t)wh*Ll*Ee;

    #pragma unroll
    for (int j = 0; j < 4; j++) {
        int g = tid + j*512;
        int plane = g >> 10, r = (g >> 3) & 127, c = g & 7;
        const __nv_bfloat16* src = (plane ? g_Plo : g_Phi) + (size_t)(m0 + r)*Ee + c*8;
        cp16(sb + plane*18432 + (r*72 + c*8)*2, src);
    }
    #pragma unroll
    for (int j = 0; j < 4; j++) {
        int g = tid + j*512;
        int plane = g >> 10, r = (g >> 3) & 127, c = g & 7;
        const __nv_bfloat16* src = (plane ? Xlo : Xhi) + (size_t)(lbase + r)*Ee + c*8;
        cp16(sb + FT_A + plane*18432 + (r*72 + c*8)*2, src);
    }
    CP_COMMIT();
    #pragma unroll
    for (int j = 0; j < 4; j++) {
        int g = tid + j*512;
        int plane = g >> 10, r = (g >> 3) & 127, c = g & 7;
        const __nv_bfloat16* src = (plane ? Xlo : Xhi) + (size_t)(lbase + 128 + r)*Ee + c*8;
        cp16(sb + FT_A + 36864 + plane*18432 + (r*72 + c*8)*2, src);
    }
    CP_COMMIT();

    const int warp_l = (wid & 3) * 32, warp_m = (wid >> 2) * 32;
    float* stage = (float*)(smem + FT_STG);
    const __nv_bfloat16* Bhi = (const __nv_bfloat16*)smem;
    const __nv_bfloat16* Blo = Bhi + 9216;

    for (int t = 0; t < 8; t++) {
        if (t < 7) { CP_WAIT1(); } else { CP_WAIT0(); }
        __syncthreads();

        const __nv_bfloat16* Ahi = (const __nv_bfloat16*)(smem + FT_A + (t & 1)*36864);
        const __nv_bfloat16* Alo = Ahi + 9216;

        FragC c[2][2];
        #pragma unroll
        for (int i = 0; i < 2; i++)
            #pragma unroll
            for (int j = 0; j < 2; j++) wmma::fill_fragment(c[i][j], 0.0f);

        #pragma unroll
        for (int k = 0; k < 4; k++) {
            FragA ahi[2], alo[2];
            #pragma unroll
            for (int i = 0; i < 2; i++) {
                wmma::load_matrix_sync(ahi[i], Ahi + (warp_l + i*16)*72 + k*16, 72);
                wmma::load_matrix_sync(alo[i], Alo + (warp_l + i*16)*72 + k*16, 72);
            }
            #pragma unroll
            for (int j = 0; j < 2; j++) {
                FragB bhi, blo;
                wmma::load_matrix_sync(bhi, Bhi + (warp_m + j*16)*72 + k*16, 72);
                wmma::load_matrix_sync(blo, Blo + (warp_m + j*16)*72 + k*16, 72);
                #pragma unroll
                for (int i = 0; i < 2; i++) {
                    wmma::mma_sync(c[i][j], ahi[i], bhi, c[i][j]);
                    wmma::mma_sync(c[i][j], ahi[i], blo, c[i][j]);
                    wmma::mma_sync(c[i][j], alo[i], bhi, c[i][j]);
                }
            }
        }

        #pragma unroll
        for (int i = 0; i < 2; i++)
            #pragma unroll
            for (int j = 0; j < 2; j++)
                wmma::store_matrix_sync(stage + (warp_l + i*16)*132 + warp_m + j*16,
                                        c[i][j], 132, wmma::mem_row_major);
        __syncthreads();

        if (t + 2 < 8) {
            #pragma unroll
            for (int j = 0; j < 4; j++) {
                int g = tid + j*512;
                int plane = g >> 10, r = (g >> 3) & 127, cc = g & 7;
                const __nv_bfloat16* src = (plane ? Xlo : Xhi)
                    + (size_t)(lbase + (t + 2)*128 + r)*Ee + cc*8;
                cp16(sb + FT_A + (t & 1)*36864 + plane*18432 + (r*72 + cc*8)*2, src);
            }
            CP_COMMIT();
        }

        {
            int row = tid >> 2;
            int l = lbase + t*128 + row;
            float rm = -CUDART_INF_F;
            float* dst = Dash + (size_t)(head*Ll + l)*Mm + m0;
            const float* srcr = stage + row*132;
            #pragma unroll
            for (int j = 0; j < 8; j++) {
                int col = (tid & 3)*4 + j*16;
                float4 v = *(const float4*)(srcr + col);
                rm = fmaxf(rm, fmaxf(fmaxf(v.x, v.y), fmaxf(v.z, v.w)));
                *(float4*)(dst + col) = v;
            }
            rm = fmaxf(rm, __shfl_xor_sync(0xffffffffu, rm, 1));
            rm = fmaxf(rm, __shfl_xor_sync(0xffffffffu, rm, 2));
            if ((tid & 3) == 0)
                g_pmax[((size_t)wh*16 + blockIdx.x)*Ll + l] = rm;
        }
    }
}

// ================== K1b: rowmax reduce + diag fold ==================
__global__ __launch_bounds__(256) void k_rmax()
{
    int gw = (blockIdx.x * 256 + threadIdx.x) >> 5;
    int lane = threadIdx.x & 31;
    int wh = gw >> 6;
    int l = (gw & 63) * 32 + lane;
    float m = -CUDART_INF_F;
    #pragma unroll
    for (int mt = 0; mt < 16; mt++)
        m = fmaxf(m, g_pmax[((size_t)wh*16 + mt)*Ll + l]);
    g_SUB[wh*Ll + l] = g_diag[wh >> 4][(wh & 15)*Ll + l] + m;
}

// ================== K2: kv — triple raw buffer, early refill ==========
// smem: raw 3x16384 @0 | Ah @49152 | Al @59392 | B 3x10240 @69632 | SUB @100352 | KS @108544
#define KV_AH   49152
#define KV_AL   59392
#define KV_B    69632
#define KV_SUB  100352
#define KV_KS   108544
#define KV_SMEM 109056
__global__ __launch_bounds__(256, 2) void k_kv()
{
    extern __shared__ char smem[];
    const uint32_t sb = smem_u32(smem);
    __nv_bfloat16* Ah = (__nv_bfloat16*)(smem + KV_AH);
    __nv_bfloat16* Al = (__nv_bfloat16*)(smem + KV_AL);
    float* SUB = (float*)(smem + KV_SUB);
    float* KS  = (float*)(smem + KV_KS);

    const int head = blockIdx.y;
    const int m0 = blockIdx.x * 128;
    const int tid = threadIdx.x, wid = tid >> 5;

    #pragma unroll
    for (int t = 0; t < 2; t++) {
        const float* srcK = g_Dk + (size_t)(head*Ll + t*32)*Mm + m0;
        uint32_t dK = sb + t*16384;
        #pragma unroll
        for (int j = 0; j < 4; j++) {
            int g = tid + j*256, row = g >> 5, col = (g & 31)*4;
            cp16(dK + (row*128 + col)*4, srcK + (size_t)row*Mm + col);
        }
        uint32_t dB = sb + KV_B + t*10240;
        #pragma unroll
        for (int j = 0; j < 2; j++) {
            int g = tid + j*256, plane = g >> 8, rem = g & 255, row = rem >> 2, cc = rem & 3;
            const __nv_bfloat16* src = (plane ? g_VTlo : g_VThi)
                + (size_t)(head*Ee + row)*Ll + t*32 + cc*8;
            cp16(dB + plane*5120 + (row*40 + cc*8)*2, src);
        }
        CP_COMMIT();
    }

    for (int i = tid; i < 2048; i += 256) {
        SUB[i] = g_SUB[(16 + head)*Ll + i];
    }
    if (tid < 128) KS[tid] = 0.0f;

    const int mA = tid & 127, sgA = (tid >> 7) * 16;
    const int warp_m = (wid & 3) * 32, warp_e = (wid >> 2) * 32;

    FragC c[2][2];
    #pragma unroll
    for (int i = 0; i < 2; i++)
        #pragma unroll
        for (int j = 0; j < 2; j++) wmma::fill_fragment(c[i][j], 0.0f);

    float ksp = 0.0f;

    for (int t = 0; t < 64; t++) {
        if (t < 63) { CP_WAIT1(); } else { CP_WAIT0(); }
        __syncthreads();   // raw(t),B(t) visible; transform(t-1)/MMA(t-1) complete

        // EARLY refill: raw(t+2) -> buf (t+2)%3 (last read by transform(t-1)),
        //               B(t+2)   -> buf (t+2)%3 (last read by MMA(t-1)) — both barrier-safe
        if (t + 2 < 64) {
            const int s1 = (t + 2) * 32;
            const float* srcK = g_Dk + (size_t)(head*Ll + s1)*Mm + m0;
            uint32_t dK = sb + ((t + 2) % 3)*16384;
            #pragma unroll
            for (int j = 0; j < 4; j++) {
                int g = tid + j*256, row = g >> 5, col = (g & 31)*4;
                cp16(dK + (row*128 + col)*4, srcK + (size_t)row*Mm + col);
            }
            uint32_t dB = sb + KV_B + ((t + 2) % 3)*10240;
            #pragma unroll
            for (int j = 0; j < 2; j++) {
                int g = tid + j*256, plane = g >> 8, rem = g & 255, row = rem >> 2, cc = rem & 3;
                const __nv_bfloat16* src = (plane ? g_VTlo : g_VThi)
                    + (size_t)(head*Ee + row)*Ll + s1 + cc*8;
                cp16(dB + plane*5120 + (row*40 + cc*8)*2, src);
            }
            CP_COMMIT();
        }

        const float* RK = (const float*)(smem + (t % 3)*16384);
        #pragma unroll
        for (int i = 0; i < 16; i += 2) {
            float f0 = RK[(sgA + i)*128 + mA];
            float f1 = RK[(sgA + i + 1)*128 + mA];
            float k0 = RATIO * (__expf(f0 - SUB[t*32 + sgA + i])     + KEPS);
            float k1 = RATIO * (__expf(f1 - SUB[t*32 + sgA + i + 1]) + KEPS);
            ksp += k0 + k1;
            uint32_t hi, lo; split2pack(k0, k1, hi, lo);
            *(uint32_t*)&Ah[mA*40 + sgA + i] = hi;
            *(uint32_t*)&Al[mA*40 + sgA + i] = lo;
        }
        __syncthreads();   // A ready

        const __nv_bfloat16* Bh = (const __nv_bfloat16*)(smem + KV_B + (t % 3)*10240);
        const __nv_bfloat16* Bl = Bh + 2560;

        #pragma unroll
        for (int k = 0; k < 2; k++) {
            FragA ahi[2], alo[2];
            #pragma unroll
            for (int i = 0; i < 2; i++) {
                wmma::load_matrix_sync(ahi[i], Ah + (warp_m + i*16)*40 + k*16, 40);
                wmma::load_matrix_sync(alo[i], Al + (warp_m + i*16)*40 + k*16, 40);
            }
            #pragma unroll
            for (int j = 0; j < 2; j++) {
                FragB bhi, blo;
                wmma::load_matrix_sync(bhi, Bh + (warp_e + j*16)*40 + k*16, 40);
                wmma::load_matrix_sync(blo, Bl + (warp_e + j*16)*40 + k*16, 40);
                #pragma unroll
                for (int i = 0; i < 2; i++) {
                    wmma::mma_sync(c[i][j], ahi[i], bhi, c[i][j]);
                    wmma::mma_sync(c[i][j], ahi[i], blo, c[i][j]);
                    wmma::mma_sync(c[i][j], alo[i], bhi, c[i][j]);
                }
            }
        }
    }

    atomicAdd(&KS[mA], ksp);
    __syncthreads();
    float* stage = (float*)smem;   // [e][m] col-major, ld 132 (raw region dead)
    #pragma unroll
    for (int i = 0; i < 2; i++)
        #pragma unroll
        for (int j = 0; j < 2; j++)
            wmma::store_matrix_sync(stage + (warp_m + i*16) + (warp_e + j*16)*132,
                                    c[i][j], 132, wmma::mem_col_major);
    __syncthreads();
    {
        int e = tid >> 2, mo = (tid & 3) * 32;
        const float* src = stage + e*132 + mo;
        __nv_bfloat16* dhi = g_Bhi + (size_t)(head*80 + e)*Mm + m0 + mo;
        __nv_bfloat16* dlo = g_Blo + (size_t)(head*80 + e)*Mm + m0 + mo;
        #pragma unroll
        for (int j = 0; j < 32; j += 2) {
            uint32_t hi, lo; split2pack(src[j], src[j+1], hi, lo);
            *(uint32_t*)(dhi + j) = hi;
            *(uint32_t*)(dlo + j) = lo;
        }
    }
    if (tid < 128) {
        __nv_bfloat16 hb, lb; split1(KS[tid], hb, lb);
        g_Bhi[(size_t)(head*80 + 64)*Mm + m0 + tid] = hb;
        g_Blo[(size_t)(head*80 + 64)*Mm + m0 + tid] = lb;
    }
}

// ================== K3: out — early B refill, N=80 incl. denominator ====
#define O_AH    36864
#define O_AL    47104
#define O_B     57344
#define O_SUBL  95744
#define O_SMEM  96256
__global__ __launch_bounds__(256, 2) void k_out(float* __restrict__ out)
{
    extern __shared__ char smem[];
    const uint32_t sb = smem_u32(smem);
    __nv_bfloat16* Ah = (__nv_bfloat16*)(smem + O_AH);
    __nv_bfloat16* Al = (__nv_bfloat16*)(smem + O_AL);
    float* SUBL = (float*)(smem + O_SUBL);

    const int head = blockIdx.y, n = head >> 3, h = head & 7;
    const int l0 = blockIdx.x * 128;
    const int tid = threadIdx.x, wid = tid >> 5;

    #pragma unroll
    for (int t = 0; t < 2; t++) {
        const float* srcQ = g_Dq + (size_t)(head*Ll + l0)*Mm + t*32;
        uint32_t dQ = sb + t*18432;
        #pragma unroll
        for (int j = 0; j < 4; j++) {
            int g = tid + j*256, l = g >> 3, col = (g & 7)*4;
            cp16(dQ + (l*36 + col)*4, srcQ + (size_t)l*Mm + col);
        }
        uint32_t dB = sb + O_B + t*12800;
        #pragma unroll
        for (int j = 0; j < 3; j++) {
            int g = tid + j*256;
            if (g < 640) {
                int plane = g / 320, q2 = g % 320, row = q2 >> 2, cc = q2 & 3;
                const __nv_bfloat16* src = (plane ? g_Blo : g_Bhi)
                    + (size_t)(head*80 + row)*Mm + t*32 + cc*8;
                cp16(dB + plane*6400 + (row*40 + cc*8)*2, src);
            }
        }
        CP_COMMIT();
    }

    if (tid < 128)
        SUBL[tid] = g_SUB[head*Ll + l0 + tid];

    const int m2 = (tid & 15) * 2, lg = (tid >> 4) * 8;
    const int warp_l = wid * 16;

    FragC c[5];
    #pragma unroll
    for (int j = 0; j < 5; j++) wmma::fill_fragment(c[j], 0.0f);

    for (int t = 0; t < 64; t++) {
        if (t < 63) { CP_WAIT1(); } else { CP_WAIT0(); }
        __syncthreads();

        // EARLY B refill (3-deep buffer; target last read by MMA(t-1), barrier-safe)
        if (t + 2 < 64) {
            const int m1 = (t + 2) * 32;
            uint32_t dB = sb + O_B + ((t + 2) % 3)*12800;
            #pragma unroll
            for (int j = 0; j < 3; j++) {
                int g = tid + j*256;
                if (g < 640) {
                    int plane = g / 320, q2 = g % 320, row = q2 >> 2, cc = q2 & 3;
                    const __nv_bfloat16* src = (plane ? g_Blo : g_Bhi)
                        + (size_t)(head*80 + row)*Mm + m1 + cc*8;
                    cp16(dB + plane*6400 + (row*40 + cc*8)*2, src);
                }
            }
        }

        const float* RQ = (const float*)(smem + (t & 1)*18432);
        #pragma unroll
        for (int i = 0; i < 8; i++) {
            int l = lg + i;
            float2 f = *(const float2*)(RQ + l*36 + m2);
            float sub = SUBL[l];
            float q0 = RATIO * (__expf(f.x - sub) + KEPS);
            float q1 = RATIO * (__expf(f.y - sub) + KEPS);
            uint32_t hi, lo; split2pack(q0, q1, hi, lo);
            *(uint32_t*)&Ah[l*40 + m2] = hi;
            *(uint32_t*)&Al[l*40 + m2] = lo;
        }
        __syncthreads();

        if (t + 2 < 64) {
            const int m1 = (t + 2) * 32;
            const float* srcQ = g_Dq + (size_t)(head*Ll + l0)*Mm + m1;
            uint32_t dQ = sb + (t & 1)*18432;
            #pragma unroll
            for (int j = 0; j < 4; j++) {
                int g = tid + j*256, l = g >> 3, col = (g & 7)*4;
                cp16(dQ + (l*36 + col)*4, srcQ + (size_t)l*Mm + col);
            }
            CP_COMMIT();   // group covers this iter's B (issued early) + Q
        }

        const __nv_bfloat16* Bh = (const __nv_bfloat16*)(smem + O_B + (t % 3)*12800);
        const __nv_bfloat16* Bl = Bh + 3200;

        #pragma unroll
        for (int k = 0; k < 2; k++) {
            FragA ahi, alo;
            wmma::load_matrix_sync(ahi, Ah + warp_l*40 + k*16, 40);
            wmma::load_matrix_sync(alo, Al + warp_l*40 + k*16, 40);
            #pragma unroll
            for (int j = 0; j < 5; j++) {
                FragB bhi, blo;
                wmma::load_matrix_sync(bhi, Bh + (j*16)*40 + k*16, 40);
                wmma::load_matrix_sync(blo, Bl + (j*16)*40 + k*16, 40);
                wmma::mma_sync(c[j], ahi, bhi, c[j]);
                wmma::mma_sync(c[j], ahi, blo, c[j]);
                wmma::mma_sync(c[j], alo, bhi, c[j]);
            }
        }
    }

    __syncthreads();
    float* stage = (float*)smem;  // [l][84]
    #pragma unroll
    for (int j = 0; j < 5; j++)
        wmma::store_matrix_sync(stage + warp_l*84 + j*16, c[j], 84, wmma::mem_row_major);
    __syncthreads();
    {
        int l = tid >> 1, ec = (tid & 1) * 32;
        float z = 1.0f / (stage[l*84 + 64] + EPSZ);
        float* dst = out + ((size_t)((n*Ll + l0 + l)*Hh + h))*Ee + ec;
        const float* src = stage + l*84 + ec;
        #pragma unroll
        for (int j = 0; j < 8; j++) {
            float4 v = *(const float4*)(src + j*4);
            *(float4*)(dst + j*4) = make_float4(v.x*z, v.y*z, v.z*z, v.w*z);
        }
    }
}

// ================== launch ==================
extern "C" void kernel_launch(void* const* d_in, const int* in_sizes, int n_in,
                              void* d_out, int out_size)
{
    const float* q = (const float*)d_in[0];
    const float* k = (const float*)d_in[1];
    const float* v = (const float*)d_in[2];
    const float* p = (const float*)d_in[3];
    float* out = (float*)d_out;

    cudaFuncSetAttribute(k_feat, cudaFuncAttributeMaxDynamicSharedMemorySize, FT_SMEM);
    cudaFuncSetAttribute(k_kv,   cudaFuncAttributeMaxDynamicSharedMemorySize, KV_SMEM);
    cudaFuncSetAttribute(k_out,  cudaFuncAttributeMaxDynamicSharedMemorySize, O_SMEM);

    k_prep<<<8448, 256>>>(q, k, p);
    k_vt<<<dim3(16, HEADS), 256>>>(v);
    k_feat<<<dim3(16, 2, 32), 512, FT_SMEM>>>();
    k_rmax<<<256, 256>>>();
    k_kv<<<dim3(16, HEADS), 256, KV_SMEM>>>();
    k_out<<<dim3(16, HEADS), 256, O_SMEM>>>(out);
}

// round 17
// speedup vs baseline: 1.3392x; 1.0059x over previous
#include <cuda_runtime.h>
#include <cuda_bf16.h>
#include <mma.h>
#include <math_constants.h>
#include <cstdint>

using namespace nvcuda;

#define Nn 2
#define Ll 2048
#define Hh 8
#define Ee 64
#define Mm 2048
#define HEADS 16
#define NLH (HEADS*Ll)

#define NRM   0.3535533905932738f
#define HNRM2 0.0625f
#define RATIO 0.022097086912079608f
#define KEPS  1e-4f
#define EPSZ  1e-6f

// ---------------- scratch ----------------
__device__ float g_Dq[(size_t)HEADS*Ll*Mm];
__device__ float g_Dk[(size_t)HEADS*Ll*Mm];
__device__ float g_diag[2][NLH];
__device__ float g_pmax[(size_t)32*16*Ll];             // [wh][mtile][l]
__device__ __nv_bfloat16 g_Xhi[(size_t)2*HEADS*Ll*Ee];
__device__ __nv_bfloat16 g_Xlo[(size_t)2*HEADS*Ll*Ee];
__device__ __nv_bfloat16 g_Phi[(size_t)Mm*Ee];
__device__ __nv_bfloat16 g_Plo[(size_t)Mm*Ee];
__device__ __nv_bfloat16 g_VThi[(size_t)HEADS*Ee*Ll];
__device__ __nv_bfloat16 g_VTlo[(size_t)HEADS*Ee*Ll];
__device__ __nv_bfloat16 g_Bhi[(size_t)HEADS*80*Mm];   // rows 0-63 kv^T, row 64 ksum
__device__ __nv_bfloat16 g_Blo[(size_t)HEADS*80*Mm];

__device__ __forceinline__ void split1(float v, __nv_bfloat16& hi, __nv_bfloat16& lo) {
    hi = __float2bfloat16_rn(v);
    lo = __float2bfloat16_rn(v - __bfloat162float(hi));
}
__device__ __forceinline__ void split2pack(float a, float b, uint32_t& hi, uint32_t& lo) {
    __nv_bfloat16 ha, la, hb, lb;
    split1(a, ha, la); split1(b, hb, lb);
    __nv_bfloat162 H = __halves2bfloat162(ha, hb), L = __halves2bfloat162(la, lb);
    hi = *(uint32_t*)&H; lo = *(uint32_t*)&L;
}

__device__ __forceinline__ uint32_t smem_u32(const void* p) {
    uint32_t a;
    asm("{ .reg .u64 t; cvta.to.shared.u64 t, %1; cvt.u32.u64 %0, t; }" : "=r"(a) : "l"(p));
    return a;
}
__device__ __forceinline__ void cp16(uint32_t s, const void* g) {
    asm volatile("cp.async.cg.shared.global [%0], [%1], 16;" :: "r"(s), "l"(g));
}
#define CP_COMMIT() asm volatile("cp.async.commit_group;" ::: "memory")
#define CP_WAIT1()  asm volatile("cp.async.wait_group 1;" ::: "memory")
#define CP_WAIT0()  asm volatile("cp.async.wait_group 0;" ::: "memory")

typedef wmma::fragment<wmma::matrix_a, 16, 16, 16, __nv_bfloat16, wmma::row_major> FragA;
typedef wmma::fragment<wmma::matrix_b, 16, 16, 16, __nv_bfloat16, wmma::col_major> FragB;
typedef wmma::fragment<wmma::accumulator, 16, 16, 16, float> FragC;

// ================== K0: prep ==================
__global__ __launch_bounds__(256) void k_prep(const float* __restrict__ q,
                                              const float* __restrict__ kk,
                                              const float* __restrict__ P)
{
    int g = blockIdx.x * 256 + threadIdx.x;
    int w = g >> 5, lane = g & 31;
    if (w < 2*NLH) {
        int which = (w >= NLH) ? 1 : 0;
        int r = which ? (w - NLH) : w;
        int head = r >> 11, l = r & (Ll - 1);
        int n = head >> 3, h = head & 7;
        const float* x = (which ? kk : q) + ((size_t)((n*Ll + l)*Hh + h))*Ee;
        float2 f = *(const float2*)(x + 2*lane);
        float s = f.x*f.x + f.y*f.y;
        #pragma unroll
        for (int o = 16; o; o >>= 1) s += __shfl_xor_sync(0xffffffffu, s, o);
        if (lane == 0) g_diag[which][r] = HNRM2 * s;
        uint32_t hi, lo; split2pack(f.x*NRM, f.y*NRM, hi, lo);
        size_t base = ((size_t)(which*HEADS + head)*Ll + l)*Ee;
        *(uint32_t*)(g_Xhi + base + 2*lane) = hi;
        *(uint32_t*)(g_Xlo + base + 2*lane) = lo;
    } else {
        int m = w - 2*NLH;
        const float* p = P + (size_t)m*Ee;
        float2 f = *(const float2*)(p + 2*lane);
        uint32_t hi, lo; split2pack(f.x, f.y, hi, lo);
        *(uint32_t*)(g_Phi + (size_t)m*Ee + 2*lane) = hi;
        *(uint32_t*)(g_Plo + (size_t)m*Ee + 2*lane) = lo;
    }
}

// ================== K0b: v -> vT split ==================
__global__ __launch_bounds__(256) void k_vt(const float* __restrict__ V)
{
    __shared__ __nv_bfloat16 sh[2][64][136];
    const int head = blockIdx.y, n = head >> 3, h = head & 7;
    const int s0 = blockIdx.x * 128;
    const int tid = threadIdx.x;

    {
        int s = tid >> 1, eh = (tid & 1) * 32;
        const float* vp = V + ((size_t)((n*Ll + s0 + s)*Hh + h))*Ee + eh;
        #pragma unroll
        for (int j = 0; j < 8; j++) {
            float4 f = *(const float4*)(vp + j*4);
            float vv[4] = {f.x, f.y, f.z, f.w};
            #pragma unroll
            for (int i = 0; i < 4; i++) {
                __nv_bfloat16 hb, lb; split1(vv[i], hb, lb);
                int e = eh + j*4 + i;
                sh[0][e][s] = hb;
                sh[1][e][s] = lb;
            }
        }
    }
    __syncthreads();
    {
        int e = tid >> 2, sc = (tid & 3) * 32;
        #pragma unroll
        for (int p = 0; p < 2; p++) {
            __nv_bfloat16* dst = (p ? g_VTlo : g_VThi) + ((size_t)(head*Ee + e))*Ll + s0 + sc;
            const uint32_t* src = (const uint32_t*)&sh[p][e][sc];
            #pragma unroll
            for (int i = 0; i < 16; i++) ((uint32_t*)dst)[i] = src[i];
        }
    }
}

// ================== K1: featurize — persistent stripe (8 tiles) ==========
#define FT_A     36864
#define FT_STG   110592
#define FT_SMEM  178176
__global__ __launch_bounds__(512, 1) void k_feat()
{
    extern __shared__ char smem[];
    const uint32_t sb = smem_u32(smem);
    const int wh = blockIdx.z;
    const int which = wh >> 4, head = wh & 15;
    const int m0 = blockIdx.x * 128;
    const int lbase = blockIdx.y * 1024;
    const int tid = threadIdx.x, wid = tid >> 5;
    float* __restrict__ Dash = which ? g_Dk : g_Dq;

    const __nv_bfloat16* Xhi = g_Xhi + (size_t)wh*Ll*Ee;
    const __nv_bfloat16* Xlo = g_Xlo + (size_t)wh*Ll*Ee;

    #pragma unroll
    for (int j = 0; j < 4; j++) {
        int g = tid + j*512;
        int plane = g >> 10, r = (g >> 3) & 127, c = g & 7;
        const __nv_bfloat16* src = (plane ? g_Plo : g_Phi) + (size_t)(m0 + r)*Ee + c*8;
        cp16(sb + plane*18432 + (r*72 + c*8)*2, src);
    }
    #pragma unroll
    for (int j = 0; j < 4; j++) {
        int g = tid + j*512;
        int plane = g >> 10, r = (g >> 3) & 127, c = g & 7;
        const __nv_bfloat16* src = (plane ? Xlo : Xhi) + (size_t)(lbase + r)*Ee + c*8;
        cp16(sb + FT_A + plane*18432 + (r*72 + c*8)*2, src);
    }
    CP_COMMIT();
    #pragma unroll
    for (int j = 0; j < 4; j++) {
        int g = tid + j*512;
        int plane = g >> 10, r = (g >> 3) & 127, c = g & 7;
        const __nv_bfloat16* src = (plane ? Xlo : Xhi) + (size_t)(lbase + 128 + r)*Ee + c*8;
        cp16(sb + FT_A + 36864 + plane*18432 + (r*72 + c*8)*2, src);
    }
    CP_COMMIT();

    const int warp_l = (wid & 3) * 32, warp_m = (wid >> 2) * 32;
    float* stage = (float*)(smem + FT_STG);
    const __nv_bfloat16* Bhi = (const __nv_bfloat16*)smem;
    const __nv_bfloat16* Blo = Bhi + 9216;

    for (int t = 0; t < 8; t++) {
        if (t < 7) { CP_WAIT1(); } else { CP_WAIT0(); }
        __syncthreads();

        const __nv_bfloat16* Ahi = (const __nv_bfloat16*)(smem + FT_A + (t & 1)*36864);
        const __nv_bfloat16* Alo = Ahi + 9216;

        FragC c[2][2];
        #pragma unroll
        for (int i = 0; i < 2; i++)
            #pragma unroll
            for (int j = 0; j < 2; j++) wmma::fill_fragment(c[i][j], 0.0f);

        #pragma unroll
        for (int k = 0; k < 4; k++) {
            FragA ahi[2], alo[2];
            #pragma unroll
            for (int i = 0; i < 2; i++) {
                wmma::load_matrix_sync(ahi[i], Ahi + (warp_l + i*16)*72 + k*16, 72);
                wmma::load_matrix_sync(alo[i], Alo + (warp_l + i*16)*72 + k*16, 72);
            }
            #pragma unroll
            for (int j = 0; j < 2; j++) {
                FragB bhi, blo;
                wmma::load_matrix_sync(bhi, Bhi + (warp_m + j*16)*72 + k*16, 72);
                wmma::load_matrix_sync(blo, Blo + (warp_m + j*16)*72 + k*16, 72);
                #pragma unroll
                for (int i = 0; i < 2; i++) {
                    wmma::mma_sync(c[i][j], ahi[i], bhi, c[i][j]);
                    wmma::mma_sync(c[i][j], ahi[i], blo, c[i][j]);
                    wmma::mma_sync(c[i][j], alo[i], bhi, c[i][j]);
                }
            }
        }

        #pragma unroll
        for (int i = 0; i < 2; i++)
            #pragma unroll
            for (int j = 0; j < 2; j++)
                wmma::store_matrix_sync(stage + (warp_l + i*16)*132 + warp_m + j*16,
                                        c[i][j], 132, wmma::mem_row_major);
        __syncthreads();

        if (t + 2 < 8) {
            #pragma unroll
            for (int j = 0; j < 4; j++) {
                int g = tid + j*512;
                int plane = g >> 10, r = (g >> 3) & 127, cc = g & 7;
                const __nv_bfloat16* src = (plane ? Xlo : Xhi)
                    + (size_t)(lbase + (t + 2)*128 + r)*Ee + cc*8;
                cp16(sb + FT_A + (t & 1)*36864 + plane*18432 + (r*72 + cc*8)*2, src);
            }
            CP_COMMIT();
        }

        {
            int row = tid >> 2;
            int l = lbase + t*128 + row;
            float rm = -CUDART_INF_F;
            float* dst = Dash + (size_t)(head*Ll + l)*Mm + m0;
            const float* srcr = stage + row*132;
            #pragma unroll
            for (int j = 0; j < 8; j++) {
                int col = (tid & 3)*4 + j*16;
                float4 v = *(const float4*)(srcr + col);
                rm = fmaxf(rm, fmaxf(fmaxf(v.x, v.y), fmaxf(v.z, v.w)));
                *(float4*)(dst + col) = v;
            }
            rm = fmaxf(rm, __shfl_xor_sync(0xffffffffu, rm, 1));
            rm = fmaxf(rm, __shfl_xor_sync(0xffffffffu, rm, 2));
            if ((tid & 3) == 0)
                g_pmax[((size_t)wh*16 + blockIdx.x)*Ll + l] = rm;
        }
    }
}

// ================== K2: kv — round-8 exact, rmax folded into prologue ======
// smem: rawK 2x16384 @0 | Ah @32768 | Al @43008 | B 3x10240 @53248 |
//       SUB 2048f @83968..92160 | KS 128f @92160..92672
#define KV_AH   32768
#define KV_AL   43008
#define KV_B    53248
#define KV_SUB  83968
#define KV_KS   92160
#define KV_SMEM 92672
__global__ __launch_bounds__(256, 2) void k_kv()
{
    extern __shared__ char smem[];
    const uint32_t sb = smem_u32(smem);
    __nv_bfloat16* Ah = (__nv_bfloat16*)(smem + KV_AH);
    __nv_bfloat16* Al = (__nv_bfloat16*)(smem + KV_AL);
    float* SUB = (float*)(smem + KV_SUB);
    float* KS  = (float*)(smem + KV_KS);

    const int head = blockIdx.y;
    const int m0 = blockIdx.x * 128;
    const int tid = threadIdx.x, wid = tid >> 5;

    #pragma unroll
    for (int t = 0; t < 2; t++) {
        const float* srcK = g_Dk + (size_t)(head*Ll + t*32)*Mm + m0;
        uint32_t dK = sb + t*16384;
        #pragma unroll
        for (int j = 0; j < 4; j++) {
            int g = tid + j*256, row = g >> 5, col = (g & 31)*4;
            cp16(dK + (row*128 + col)*4, srcK + (size_t)row*Mm + col);
        }
        uint32_t dB = sb + KV_B + t*10240;
        #pragma unroll
        for (int j = 0; j < 2; j++) {
            int g = tid + j*256, plane = g >> 8, rem = g & 255, row = rem >> 2, cc = rem & 3;
            const __nv_bfloat16* src = (plane ? g_VTlo : g_VThi)
                + (size_t)(head*Ee + row)*Ll + t*32 + cc*8;
            cp16(dB + plane*5120 + (row*40 + cc*8)*2, src);
        }
        CP_COMMIT();
    }

    // SUB = diag + rowmax(pmax over 16 m-tiles), inline (k_rmax folded)
    {
        const int wh = 16 + head;
        for (int i = tid; i < 2048; i += 256) {
            float m = -CUDART_INF_F;
            #pragma unroll
            for (int mt = 0; mt < 16; mt++)
                m = fmaxf(m, g_pmax[((size_t)wh*16 + mt)*Ll + i]);
            SUB[i] = g_diag[1][head*Ll + i] + m;
        }
    }
    if (tid < 128) KS[tid] = 0.0f;

    const int mA = tid & 127, sgA = (tid >> 7) * 16;
    const int warp_m = (wid & 3) * 32, warp_e = (wid >> 2) * 32;

    FragC c[2][2];
    #pragma unroll
    for (int i = 0; i < 2; i++)
        #pragma unroll
        for (int j = 0; j < 2; j++) wmma::fill_fragment(c[i][j], 0.0f);

    float ksp = 0.0f;

    for (int t = 0; t < 64; t++) {
        if (t < 63) { CP_WAIT1(); } else { CP_WAIT0(); }
        __syncthreads();

        const float* RK = (const float*)(smem + (t & 1)*16384);

        #pragma unroll
        for (int i = 0; i < 16; i += 2) {
            float f0 = RK[(sgA + i)*128 + mA];
            float f1 = RK[(sgA + i + 1)*128 + mA];
            float k0 = RATIO * (__expf(f0 - SUB[t*32 + sgA + i])     + KEPS);
            float k1 = RATIO * (__expf(f1 - SUB[t*32 + sgA + i + 1]) + KEPS);
            ksp += k0 + k1;
            uint32_t hi, lo; split2pack(k0, k1, hi, lo);
            *(uint32_t*)&Ah[mA*40 + sgA + i] = hi;
            *(uint32_t*)&Al[mA*40 + sgA + i] = lo;
        }
        __syncthreads();

        if (t + 2 < 64) {
            const int s1 = (t + 2) * 32;
            const float* srcK = g_Dk + (size_t)(head*Ll + s1)*Mm + m0;
            uint32_t dK = sb + (t & 1)*16384;
            #pragma unroll
            for (int j = 0; j < 4; j++) {
                int g = tid + j*256, row = g >> 5, col = (g & 31)*4;
                cp16(dK + (row*128 + col)*4, srcK + (size_t)row*Mm + col);
            }
            uint32_t dB = sb + KV_B + ((t + 2) % 3)*10240;
            #pragma unroll
            for (int j = 0; j < 2; j++) {
                int g = tid + j*256, plane = g >> 8, rem = g & 255, row = rem >> 2, cc = rem & 3;
                const __nv_bfloat16* src = (plane ? g_VTlo : g_VThi)
                    + (size_t)(head*Ee + row)*Ll + s1 + cc*8;
                cp16(dB + plane*5120 + (row*40 + cc*8)*2, src);
            }
            CP_COMMIT();
        }

        const __nv_bfloat16* Bh = (const __nv_bfloat16*)(smem + KV_B + (t % 3)*10240);
        const __nv_bfloat16* Bl = Bh + 2560;

        #pragma unroll
        for (int k = 0; k < 2; k++) {
            FragA ahi[2], alo[2];
            #pragma unroll
            for (int i = 0; i < 2; i++) {
                wmma::load_matrix_sync(ahi[i], Ah + (warp_m + i*16)*40 + k*16, 40);
                wmma::load_matrix_sync(alo[i], Al + (warp_m + i*16)*40 + k*16, 40);
            }
            #pragma unroll
            for (int j = 0; j < 2; j++) {
                FragB bhi, blo;
                wmma::load_matrix_sync(bhi, Bh + (warp_e + j*16)*40 + k*16, 40);
                wmma::load_matrix_sync(blo, Bl + (warp_e + j*16)*40 + k*16, 40);
                #pragma unroll
                for (int i = 0; i < 2; i++) {
                    wmma::mma_sync(c[i][j], ahi[i], bhi, c[i][j]);
                    wmma::mma_sync(c[i][j], ahi[i], blo, c[i][j]);
                    wmma::mma_sync(c[i][j], alo[i], bhi, c[i][j]);
                }
            }
        }
    }

    atomicAdd(&KS[mA], ksp);
    __syncthreads();
    float* stage = (float*)smem;
    #pragma unroll
    for (int i = 0; i < 2; i++)
        #pragma unroll
        for (int j = 0; j < 2; j++)
            wmma::store_matrix_sync(stage + (warp_m + i*16) + (warp_e + j*16)*132,
                                    c[i][j], 132, wmma::mem_col_major);
    __syncthreads();
    {
        int e = tid >> 2, mo = (tid & 3) * 32;
        const float* src = stage + e*132 + mo;
        __nv_bfloat16* dhi = g_Bhi + (size_t)(head*80 + e)*Mm + m0 + mo;
        __nv_bfloat16* dlo = g_Blo + (size_t)(head*80 + e)*Mm + m0 + mo;
        #pragma unroll
        for (int j = 0; j < 32; j += 2) {
            uint32_t hi, lo; split2pack(src[j], src[j+1], hi, lo);
            *(uint32_t*)(dhi + j) = hi;
            *(uint32_t*)(dlo + j) = lo;
        }
    }
    if (tid < 128) {
        __nv_bfloat16 hb, lb; split1(KS[tid], hb, lb);
        g_Bhi[(size_t)(head*80 + 64)*Mm + m0 + tid] = hb;
        g_Blo[(size_t)(head*80 + 64)*Mm + m0 + tid] = lb;
    }
}

// ================== K3: out — round-8 exact, rmax folded into prologue ====
#define O_AH    36864
#define O_AL    47104
#define O_B     57344
#define O_SUBL  95744
#define O_SMEM  96256
__global__ __launch_bounds__(256, 2) void k_out(float* __restrict__ out)
{
    extern __shared__ char smem[];
    const uint32_t sb = smem_u32(smem);
    __nv_bfloat16* Ah = (__nv_bfloat16*)(smem + O_AH);
    __nv_bfloat16* Al = (__nv_bfloat16*)(smem + O_AL);
    float* SUBL = (float*)(smem + O_SUBL);

    const int head = blockIdx.y, n = head >> 3, h = head & 7;
    const int l0 = blockIdx.x * 128;
    const int tid = threadIdx.x, wid = tid >> 5;

    #pragma unroll
    for (int t = 0; t < 2; t++) {
        const float* srcQ = g_Dq + (size_t)(head*Ll + l0)*Mm + t*32;
        uint32_t dQ = sb + t*18432;
        #pragma unroll
        for (int j = 0; j < 4; j++) {
            int g = tid + j*256, l = g >> 3, col = (g & 7)*4;
            cp16(dQ + (l*36 + col)*4, srcQ + (size_t)l*Mm + col);
        }
        uint32_t dB = sb + O_B + t*12800;
        #pragma unroll
        for (int j = 0; j < 3; j++) {
            int g = tid + j*256;
            if (g < 640) {
                int plane = g / 320, q2 = g % 320, row = q2 >> 2, cc = q2 & 3;
                const __nv_bfloat16* src = (plane ? g_Blo : g_Bhi)
                    + (size_t)(head*80 + row)*Mm + t*32 + cc*8;
                cp16(dB + plane*6400 + (row*40 + cc*8)*2, src);
            }
        }
        CP_COMMIT();
    }

    if (tid < 128) {
        int l = l0 + tid;
        float m = -CUDART_INF_F;
        #pragma unroll
        for (int mt = 0; mt < 16; mt++)
            m = fmaxf(m, g_pmax[((size_t)head*16 + mt)*Ll + l]);
        SUBL[tid] = g_diag[0][head*Ll + l] + m;
    }

    const int m2 = (tid & 15) * 2, lg = (tid >> 4) * 8;
    const int warp_l = wid * 16;

    FragC c[5];
    #pragma unroll
    for (int j = 0; j < 5; j++) wmma::fill_fragment(c[j], 0.0f);

    for (int t = 0; t < 64; t++) {
        if (t < 63) { CP_WAIT1(); } else { CP_WAIT0(); }
        __syncthreads();

        const float* RQ = (const float*)(smem + (t & 1)*18432);

        #pragma unroll
        for (int i = 0; i < 8; i++) {
            int l = lg + i;
            float2 f = *(const float2*)(RQ + l*36 + m2);
            float sub = SUBL[l];
            float q0 = RATIO * (__expf(f.x - sub) + KEPS);
            float q1 = RATIO * (__expf(f.y - sub) + KEPS);
            uint32_t hi, lo; split2pack(q0, q1, hi, lo);
            *(uint32_t*)&Ah[l*40 + m2] = hi;
            *(uint32_t*)&Al[l*40 + m2] = lo;
        }
        __syncthreads();

        if (t + 2 < 64) {
            const int m1 = (t + 2) * 32;
            const float* srcQ = g_Dq + (size_t)(head*Ll + l0)*Mm + m1;
            uint32_t dQ = sb + (t & 1)*18432;
            #pragma unroll
            for (int j = 0; j < 4; j++) {
                int g = tid + j*256, l = g >> 3, col = (g & 7)*4;
                cp16(dQ + (l*36 + col)*4, srcQ + (size_t)l*Mm + col);
            }
            uint32_t dB = sb + O_B + ((t + 2) % 3)*12800;
            #pragma unroll
            for (int j = 0; j < 3; j++) {
                int g = tid + j*256;
                if (g < 640) {
                    int plane = g / 320, q2 = g % 320, row = q2 >> 2, cc = q2 & 3;
                    const __nv_bfloat16* src = (plane ? g_Blo : g_Bhi)
                        + (size_t)(head*80 + row)*Mm + m1 + cc*8;
                    cp16(dB + plane*6400 + (row*40 + cc*8)*2, src);
                }
            }
            CP_COMMIT();
        }

        const __nv_bfloat16* Bh = (const __nv_bfloat16*)(smem + O_B + (t % 3)*12800);
        const __nv_bfloat16* Bl = Bh + 3200;

        #pragma unroll
        for (int k = 0; k < 2; k++) {
            FragA ahi, alo;
            wmma::load_matrix_sync(ahi, Ah + warp_l*40 + k*16, 40);
            wmma::load_matrix_sync(alo, Al + warp_l*40 + k*16, 40);
            #pragma unroll
            for (int j = 0; j < 5; j++) {
                FragB bhi, blo;
                wmma::load_matrix_sync(bhi, Bh + (j*16)*40 + k*16, 40);
                wmma::load_matrix_sync(blo, Bl + (j*16)*40 + k*16, 40);
                wmma::mma_sync(c[j], ahi, bhi, c[j]);
                wmma::mma_sync(c[j], ahi, blo, c[j]);
                wmma::mma_sync(c[j], alo, bhi, c[j]);
            }
        }
    }

    __syncthreads();
    float* stage = (float*)smem;  // [l][84]
    #pragma unroll
    for (int j = 0; j < 5; j++)
        wmma::store_matrix_sync(stage + warp_l*84 + j*16, c[j], 84, wmma::mem_row_major);
    __syncthreads();
    {
        int l = tid >> 1, ec = (tid & 1) * 32;
        float z = 1.0f / (stage[l*84 + 64] + EPSZ);
        float* dst = out + ((size_t)((n*Ll + l0 + l)*Hh + h))*Ee + ec;
        const float* src = stage + l*84 + ec;
        #pragma unroll
        for (int j = 0; j < 8; j++) {
            float4 v = *(const float4*)(src + j*4);
            *(float4*)(dst + j*4) = make_float4(v.x*z, v.y*z, v.z*z, v.w*z);
        }
    }
}

// ================== launch ==================
extern "C" void kernel_launch(void* const* d_in, const int* in_sizes, int n_in,
                              void* d_out, int out_size)
{
    const float* q = (const float*)d_in[0];
    const float* k = (const float*)d_in[1];
    const float* v = (const float*)d_in[2];
    const float* p = (const float*)d_in[3];
    float* out = (float*)d_out;

    cudaFuncSetAttribute(k_feat, cudaFuncAttributeMaxDynamicSharedMemorySize, FT_SMEM);
    cudaFuncSetAttribute(k_kv,   cudaFuncAttributeMaxDynamicSharedMemorySize, KV_SMEM);
    cudaFuncSetAttribute(k_out,  cudaFuncAttributeMaxDynamicSharedMemorySize, O_SMEM);

    k_prep<<<8448, 256>>>(q, k, p);
    k_vt<<<dim3(16, HEADS), 256>>>(v);
    k_feat<<<dim3(16, 2, 32), 512, FT_SMEM>>>();
    k_kv<<<dim3(16, HEADS), 256, KV_SMEM>>>();
    k_out<<<dim3(16, HEADS), 256, O_SMEM>>>(out);
}